// round 4
// baseline (speedup 1.0000x reference)
#include <cuda_runtime.h>
#include <math.h>

#define NPTS   2048
#define NT     512
#define EPT    4
#define NW     (NT/32)      // 16 warps
#define MAXPTS 100
#define NBAT   2
#define F_INF  (__int_as_float(0x7f800000))

typedef unsigned long long u64;
typedef unsigned int       u32;

static __device__ __forceinline__ u64 umin64(u64 a, u64 b) { return a < b ? a : b; }
static __device__ __forceinline__ u64 umax64(u64 a, u64 b) { return a > b ? a : b; }

struct Smem {
    float4 spt[NBAT][NPTS];                  // (-2x,-2y,-2z,|x|^2)
    float  sdeath[NBAT][NPTS];
    u64    wred[NBAT][2][NW];                // 16B-aligned
};

__global__ __launch_bounds__(NT, 1)
void ph_kernel(const float* __restrict__ x,
               const float* __restrict__ filt,
               float* __restrict__ out,
               int B, int F)
{
    extern __shared__ char smraw[];
    Smem* sm = reinterpret_cast<Smem*>(smraw);

    const int tid   = threadIdx.x;
    const int lane  = tid & 31;
    const int wid   = tid >> 5;
    const int gbase = tid << 2;             // 4 elements per thread
    const float inf = F_INF;

    const int b0 = blockIdx.x * NBAT;
    int   bidx[NBAT];
    bool  bval[NBAT];
    #pragma unroll
    for (int bb = 0; bb < NBAT; bb++) {
        int gb = b0 + bb;
        bval[bb] = (gb < B);
        bidx[bb] = bval[bb] ? gb : (B - 1);  // clamp: compute on dup, skip writes
    }

    // ---- load both batches: coords in regs (4/thread/chain), float4 in smem ----
    float rx[NBAT][EPT], ry[NBAT][EPT], rz[NBAT][EPT], rsq[NBAT][EPT], mk[NBAT][EPT];
    #pragma unroll
    for (int bb = 0; bb < NBAT; bb++) {
        const float* xb = x + (long)bidx[bb] * NPTS * 3;
        #pragma unroll
        for (int e = 0; e < EPT; e++) {
            int i = gbase + e;
            float a = xb[3*i + 0];
            float c = xb[3*i + 1];
            float d = xb[3*i + 2];
            rx[bb][e] = a; ry[bb][e] = c; rz[bb][e] = d;
            float s = fmaf(a, a, fmaf(c, c, d * d));
            rsq[bb][e] = s; mk[bb][e] = inf;
            sm->spt[bb][i] = make_float4(-2.0f * a, -2.0f * c, -2.0f * d, s);
        }
    }
    __syncthreads();

    // ---- dual interleaved Prim: one barrier per round serves BOTH chains ----
    int j[NBAT]; j[0] = 0; j[1] = 0;
    int p = 0;

    #pragma unroll 1
    for (int step = 0; step < NPTS - 1; step++) {
        #pragma unroll
        for (int bb = 0; bb < NBAT; bb++) {
            float4 pj = sm->spt[bb][j[bb]];       // LDS.128 broadcast

            u64 pk[EPT];
            #pragma unroll
            for (int e = 0; e < EPT; e++) {
                int gi = gbase + e;
                bool rem = (gi == j[bb]);
                float rs = rem ? inf : rsq[bb][e]; // permanent poison
                rsq[bb][e] = rs;
                float acc = fmaf(pj.x, rx[bb][e], rs + pj.w);
                acc = fmaf(pj.y, ry[bb][e], acc);
                acc = fmaf(pj.z, rz[bb][e], acc);
                acc = fmaxf(acc, 0.0f);            // >=0 -> u32 bit-order exact
                float m = fminf(mk[bb][e], acc);
                m = rem ? inf : m;
                mk[bb][e] = m;
                pk[e] = ((u64)__float_as_uint(m) << 32) | (u32)gi;
            }
            u64 t0 = umin64(pk[0], pk[1]);
            u64 t1 = umin64(pk[2], pk[3]);
            t0 = umin64(t0, t1);

            u32 vb = (u32)(t0 >> 32);
            u32 ti = (u32)t0;
            u32 r1 = __reduce_min_sync(0xffffffffu, vb);
            u32 ik = (vb == r1) ? ti : 0xffffffffu;
            u32 r2 = __reduce_min_sync(0xffffffffu, ik);
            if (lane == 0) sm->wred[bb][p][wid] = ((u64)r1 << 32) | (u64)r2;
        }
        __syncthreads();

        #pragma unroll
        for (int bb = 0; bb < NBAT; bb++) {
            const ulonglong2* w2 =
                reinterpret_cast<const ulonglong2*>(&sm->wred[bb][p][0]);
            u64 m0, m1, m2, m3;
            {
                ulonglong2 a = w2[0], c = w2[1], d = w2[2], g = w2[3];
                m0 = umin64(a.x, a.y); m1 = umin64(c.x, c.y);
                m2 = umin64(d.x, d.y); m3 = umin64(g.x, g.y);
            }
            {
                ulonglong2 a = w2[4], c = w2[5], d = w2[6], g = w2[7];
                m0 = umin64(m0, umin64(a.x, a.y));
                m1 = umin64(m1, umin64(c.x, c.y));
                m2 = umin64(m2, umin64(d.x, d.y));
                m3 = umin64(m3, umin64(g.x, g.y));
            }
            m0 = umin64(m0, m1); m2 = umin64(m2, m3); m0 = umin64(m0, m2);
            if (tid == 0) sm->sdeath[bb][step] = __uint_as_float((u32)(m0 >> 32));
            j[bb] = (int)(u32)m0;
        }
        p ^= 1;
    }
    __syncthreads();

    // ---- d^2 -> sqrt; pad slot 2047 with +INF ----
    #pragma unroll
    for (int bb = 0; bb < NBAT; bb++) {
        #pragma unroll
        for (int e = 0; e < EPT; e++) {
            int i = gbase + e;
            float d2 = sm->sdeath[bb][i];
            sm->sdeath[bb][i] = (i < NPTS - 1) ? sqrtf(d2) : inf;
        }
    }
    __syncthreads();

    const long bet0 = (long)B * 3 * MAXPTS * 2;

    // ---- zero-fill H1/H2 diagram slices and betti rows 1,2 ----
    #pragma unroll
    for (int bb = 0; bb < NBAT; bb++) {
        if (!bval[bb]) continue;
        long dgm_base = (long)bidx[bb] * 3 * MAXPTS * 2;
        long bet_base = bet0 + (long)bidx[bb] * 3 * F;
        for (int i = tid; i < 2 * MAXPTS * 2; i += NT)
            out[dgm_base + MAXPTS * 2 + i] = 0.0f;
        for (int i = tid; i < 2 * F; i += NT)
            out[bet_base + F + i] = 0.0f;
    }

    // ---- Betti-0: block halves handle batch A / B in parallel ----
    {
        int bb = tid >> 8;            // 0 or 1 (256 threads each)
        int lt = tid & 255;
        if (bval[bb]) {
            long bet_base = bet0 + (long)bidx[bb] * 3 * F;
            for (int fi = lt; fi < F; fi += NT / NBAT) {
                float ff = filt[fi];
                int cnt = 0;
                for (int i = 0; i < NPTS; i += 4) {
                    float4 v = *reinterpret_cast<const float4*>(&sm->sdeath[bb][i]);
                    cnt += (v.x <= ff) + (v.y <= ff) + (v.z <= ff) + (v.w <= ff);
                }
                out[bet_base + fi] = (float)(NPTS - cnt);
            }
        }
    }
    __syncthreads();

    // ---- top-100 deaths desc: dual interleaved iterative max extraction ----
    int jp[NBAT]; jp[0] = -1; jp[1] = -1;
    p = 0;
    #pragma unroll 1
    for (int k = 0; k < MAXPTS; k++) {
        #pragma unroll
        for (int bb = 0; bb < NBAT; bb++) {
            u64 pk[EPT];
            #pragma unroll
            for (int e = 0; e < EPT; e++) {
                int gi = gbase + e;
                float v = sm->sdeath[bb][gi];
                v = (gi == jp[bb] || gi == NPTS - 1) ? 0.0f : v;
                pk[e] = ((u64)__float_as_uint(v) << 32) | (u32)gi;
            }
            u64 t0 = umax64(pk[0], pk[1]);
            u64 t1 = umax64(pk[2], pk[3]);
            t0 = umax64(t0, t1);

            u32 vb = (u32)(t0 >> 32);
            u32 ti = (u32)t0;
            u32 r1 = __reduce_max_sync(0xffffffffu, vb);
            u32 ik = (vb == r1) ? ti : 0u;
            u32 r2 = __reduce_max_sync(0xffffffffu, ik);
            if (lane == 0) sm->wred[bb][p][wid] = ((u64)r1 << 32) | (u64)r2;
        }
        if (tid == 0) {
            #pragma unroll
            for (int bb = 0; bb < NBAT; bb++)
                if (jp[bb] >= 0) sm->sdeath[bb][jp[bb]] = 0.0f;  // persist removal
        }
        __syncthreads();

        #pragma unroll
        for (int bb = 0; bb < NBAT; bb++) {
            const ulonglong2* w2 =
                reinterpret_cast<const ulonglong2*>(&sm->wred[bb][p][0]);
            u64 m0, m1, m2, m3;
            {
                ulonglong2 a = w2[0], c = w2[1], d = w2[2], g = w2[3];
                m0 = umax64(a.x, a.y); m1 = umax64(c.x, c.y);
                m2 = umax64(d.x, d.y); m3 = umax64(g.x, g.y);
            }
            {
                ulonglong2 a = w2[4], c = w2[5], d = w2[6], g = w2[7];
                m0 = umax64(m0, umax64(a.x, a.y));
                m1 = umax64(m1, umax64(c.x, c.y));
                m2 = umax64(m2, umax64(d.x, d.y));
                m3 = umax64(m3, umax64(g.x, g.y));
            }
            m0 = umax64(m0, m1); m2 = umax64(m2, m3); m0 = umax64(m0, m2);
            if (tid == 0 && bval[bb]) {
                long dgm_base = (long)bidx[bb] * 3 * MAXPTS * 2;
                out[dgm_base + 2 * k + 0] = 0.0f;
                out[dgm_base + 2 * k + 1] = __uint_as_float((u32)(m0 >> 32));
            }
            jp[bb] = (int)(u32)m0;
        }
        p ^= 1;
    }
}

extern "C" void kernel_launch(void* const* d_in, const int* in_sizes, int n_in,
                              void* d_out, int out_size)
{
    const float* x    = (const float*)d_in[0];
    const float* filt = (const float*)d_in[1];
    float* out        = (float*)d_out;

    int B = in_sizes[0] / (NPTS * 3);
    int F = in_sizes[1];
    int grid = (B + NBAT - 1) / NBAT;

    cudaFuncSetAttribute(ph_kernel,
                         cudaFuncAttributeMaxDynamicSharedMemorySize,
                         (int)sizeof(Smem));
    ph_kernel<<<grid, NT, sizeof(Smem)>>>(x, filt, out, B, F);
}

// round 5
// speedup vs baseline: 1.7935x; 1.7935x over previous
#include <cuda_runtime.h>
#include <math.h>

#define NPTS   2048
#define NTH    256          // threads per half-block (one batch)
#define NT     512          // total threads = 2 half-blocks
#define EPT    8
#define NWH    (NTH/32)     // 8 warps per half
#define MAXPTS 100
#define NBAT   2
#define F_INF  (__int_as_float(0x7f800000))

typedef unsigned long long u64;
typedef unsigned int       u32;

static __device__ __forceinline__ u64 umin64(u64 a, u64 b) { return a < b ? a : b; }
static __device__ __forceinline__ u64 umax64(u64 a, u64 b) { return a > b ? a : b; }

struct Smem {
    float4 spt[NBAT][NPTS];                  // (-2x,-2y,-2z,|x|^2)
    float  sdeath[NBAT][NPTS];
    u64    wred[NBAT][2][NWH];               // 16B-aligned
};

__global__ __launch_bounds__(NT, 1)
void ph_kernel(const float* __restrict__ x,
               const float* __restrict__ filt,
               float* __restrict__ out,
               int B, int F)
{
    extern __shared__ char smraw[];
    Smem* sm = reinterpret_cast<Smem*>(smraw);

    const int tid   = threadIdx.x;
    const int bb    = tid >> 8;              // 0: warps 0-7, 1: warps 8-15
    const int ltid  = tid & (NTH - 1);       // thread id within half
    const int lane  = tid & 31;
    const int lwid  = (tid >> 5) & (NWH - 1);// warp id within half
    const int gbase = ltid << 3;
    const float inf = F_INF;

    const int  gb   = blockIdx.x * NBAT + bb;
    const bool bval = (gb < B);
    const int  bidx = bval ? gb : (B - 1);   // clamp: compute on dup, skip writes

    // ---- load own batch: coords in regs, premultiplied float4 in smem ----
    float rx[EPT], ry[EPT], rz[EPT], rsq[EPT], mk[EPT];
    {
        const float* xb = x + (long)bidx * NPTS * 3;
        #pragma unroll
        for (int e = 0; e < EPT; e++) {
            int i = gbase + e;
            float a = xb[3*i + 0];
            float c = xb[3*i + 1];
            float d = xb[3*i + 2];
            rx[e] = a; ry[e] = c; rz[e] = d;
            float s = fmaf(a, a, fmaf(c, c, d * d));
            rsq[e] = s; mk[e] = inf;
            sm->spt[bb][i] = make_float4(-2.0f * a, -2.0f * c, -2.0f * d, s);
        }
    }
    __syncthreads();

    // ---- Prim's MST: two independent chains, one shared barrier per step ----
    int j = 0;
    int p = 0;

    #pragma unroll 1
    for (int step = 0; step < NPTS - 1; step++) {
        float4 pj = sm->spt[bb][j];          // LDS.128 broadcast within half

        u64 pk[EPT];
        #pragma unroll
        for (int e = 0; e < EPT; e++) {
            int gi = gbase + e;
            bool rem = (gi == j);
            float rs = rem ? inf : rsq[e];   // permanent poison of removed vertex
            rsq[e] = rs;
            float acc = fmaf(pj.x, rx[e], rs + pj.w);
            acc = fmaf(pj.y, ry[e], acc);
            acc = fmaf(pj.z, rz[e], acc);
            acc = fmaxf(acc, 0.0f);          // >=0 -> u32 bit-order exact
            float m = fminf(mk[e], acc);
            m = rem ? inf : m;
            mk[e] = m;
            pk[e] = ((u64)__float_as_uint(m) << 32) | (u32)gi;
        }
        // 3-level pack tree (low-latency per-thread argmin)
        u64 t0 = umin64(pk[0], pk[1]);
        u64 t1 = umin64(pk[2], pk[3]);
        u64 t2 = umin64(pk[4], pk[5]);
        u64 t3 = umin64(pk[6], pk[7]);
        t0 = umin64(t0, t1); t2 = umin64(t2, t3); t0 = umin64(t0, t2);

        u32 vb = (u32)(t0 >> 32);
        u32 ti = (u32)t0;
        u32 r1 = __reduce_min_sync(0xffffffffu, vb);
        u32 ik = (vb == r1) ? ti : 0xffffffffu;
        u32 r2 = __reduce_min_sync(0xffffffffu, ik);
        if (lane == 0) sm->wred[bb][p][lwid] = ((u64)r1 << 32) | (u64)r2;

        __syncthreads();

        // cross-warp final reduce over own half's 8 slots (redundant per thread)
        {
            const ulonglong2* w2 =
                reinterpret_cast<const ulonglong2*>(&sm->wred[bb][p][0]);
            ulonglong2 a = w2[0], c = w2[1], d = w2[2], g = w2[3];
            u64 m0 = umin64(a.x, a.y);
            u64 m1 = umin64(c.x, c.y);
            u64 m2 = umin64(d.x, d.y);
            u64 m3 = umin64(g.x, g.y);
            m0 = umin64(m0, m1); m2 = umin64(m2, m3); m0 = umin64(m0, m2);
            if (ltid == 0) sm->sdeath[bb][step] = __uint_as_float((u32)(m0 >> 32));
            j = (int)(u32)m0;
        }
        p ^= 1;
    }
    __syncthreads();

    // ---- d^2 -> sqrt; pad slot 2047 with +INF ----
    #pragma unroll
    for (int e = 0; e < EPT; e++) {
        int i = gbase + e;
        float d2 = sm->sdeath[bb][i];
        sm->sdeath[bb][i] = (i < NPTS - 1) ? sqrtf(d2) : inf;
    }
    __syncthreads();

    const long bet0     = (long)B * 3 * MAXPTS * 2;
    const long dgm_base = (long)bidx * 3 * MAXPTS * 2;
    const long bet_base = bet0 + (long)bidx * 3 * F;

    // ---- zero-fill H1/H2 diagram slices + betti rows 1,2 (each half its batch) ----
    if (bval) {
        for (int i = ltid; i < 2 * MAXPTS * 2; i += NTH)
            out[dgm_base + MAXPTS * 2 + i] = 0.0f;
        for (int i = ltid; i < 2 * F; i += NTH)
            out[bet_base + F + i] = 0.0f;

        // ---- Betti-0: one threshold per thread, float4 smem scan ----
        if (ltid < F) {
            float ff = filt[ltid];
            int cnt = 0;
            for (int i = 0; i < NPTS; i += 4) {
                float4 v = *reinterpret_cast<const float4*>(&sm->sdeath[bb][i]);
                cnt += (v.x <= ff) + (v.y <= ff) + (v.z <= ff) + (v.w <= ff);
            }
            out[bet_base + ltid] = (float)(NPTS - cnt);
        }
    }
    __syncthreads();

    // ---- top-100 deaths desc: two independent extractions, shared barrier ----
    int jp = -1;
    p = 0;
    #pragma unroll 1
    for (int k = 0; k < MAXPTS; k++) {
        u64 pk[EPT];
        #pragma unroll
        for (int e = 0; e < EPT; e++) {
            int gi = gbase + e;
            float v = sm->sdeath[bb][gi];
            v = (gi == jp || gi == NPTS - 1) ? 0.0f : v;  // mask pending + INF pad
            pk[e] = ((u64)__float_as_uint(v) << 32) | (u32)gi;
        }
        u64 t0 = umax64(pk[0], pk[1]);
        u64 t1 = umax64(pk[2], pk[3]);
        u64 t2 = umax64(pk[4], pk[5]);
        u64 t3 = umax64(pk[6], pk[7]);
        t0 = umax64(t0, t1); t2 = umax64(t2, t3); t0 = umax64(t0, t2);

        u32 vb = (u32)(t0 >> 32);
        u32 ti = (u32)t0;
        u32 r1 = __reduce_max_sync(0xffffffffu, vb);
        u32 ik = (vb == r1) ? ti : 0u;
        u32 r2 = __reduce_max_sync(0xffffffffu, ik);
        if (lane == 0) sm->wred[bb][p][lwid] = ((u64)r1 << 32) | (u64)r2;
        if (ltid == 0 && jp >= 0) sm->sdeath[bb][jp] = 0.0f;   // persist removal

        __syncthreads();

        {
            const ulonglong2* w2 =
                reinterpret_cast<const ulonglong2*>(&sm->wred[bb][p][0]);
            ulonglong2 a = w2[0], c = w2[1], d = w2[2], g = w2[3];
            u64 m0 = umax64(a.x, a.y);
            u64 m1 = umax64(c.x, c.y);
            u64 m2 = umax64(d.x, d.y);
            u64 m3 = umax64(g.x, g.y);
            m0 = umax64(m0, m1); m2 = umax64(m2, m3); m0 = umax64(m0, m2);
            if (ltid == 0 && bval) {
                out[dgm_base + 2 * k + 0] = 0.0f;                          // birth
                out[dgm_base + 2 * k + 1] = __uint_as_float((u32)(m0 >> 32)); // death
            }
            jp = (int)(u32)m0;
        }
        p ^= 1;
    }
}

extern "C" void kernel_launch(void* const* d_in, const int* in_sizes, int n_in,
                              void* d_out, int out_size)
{
    const float* x    = (const float*)d_in[0];
    const float* filt = (const float*)d_in[1];
    float* out        = (float*)d_out;

    int B = in_sizes[0] / (NPTS * 3);
    int F = in_sizes[1];
    int grid = (B + NBAT - 1) / NBAT;

    cudaFuncSetAttribute(ph_kernel,
                         cudaFuncAttributeMaxDynamicSharedMemorySize,
                         (int)sizeof(Smem));
    ph_kernel<<<grid, NT, sizeof(Smem)>>>(x, filt, out, B, F);
}

// round 6
// speedup vs baseline: 1.8906x; 1.0541x over previous
#include <cuda_runtime.h>
#include <math.h>

#define NPTS   2048
#define NTH    256          // threads per half (one batch)
#define NT     512
#define EPT    8
#define NWH    (NTH/32)     // 8 warps per half
#define MAXPTS 100
#define NBAT   2
#define F_INF  (__int_as_float(0x7f800000))

typedef unsigned long long u64;
typedef unsigned int       u32;

static __device__ __forceinline__ u64 umin64(u64 a, u64 b) { return a < b ? a : b; }
static __device__ __forceinline__ u64 umax64(u64 a, u64 b) { return a > b ? a : b; }

struct Smem {
    float4 spt[NBAT][NPTS];                  // (-2x,-2y,-2z,|x|^2)
    float  sdeath[NBAT][NPTS];
    u64    wred[NBAT][2][NWH];
};

__global__ __launch_bounds__(NT, 1)
void ph_kernel(const float* __restrict__ x,
               const float* __restrict__ filt,
               float* __restrict__ out,
               int B, int F)
{
    extern __shared__ char smraw[];
    Smem* sm = reinterpret_cast<Smem*>(smraw);

    const int tid   = threadIdx.x;
    const int bb    = tid >> 8;              // half id: 0 = warps 0-7, 1 = warps 8-15
    const int ltid  = tid & (NTH - 1);
    const int lane  = tid & 31;
    const int lwid  = (tid >> 5) & (NWH - 1);
    const int gbase = ltid << 3;
    const float inf = F_INF;

    const int  gb   = blockIdx.x * NBAT + bb;
    const bool bval = (gb < B);
    const int  bidx = bval ? gb : (B - 1);   // clamp: compute on dup, skip writes

    // ---- load own batch: coords in regs, premultiplied float4 in smem ----
    float rx[EPT], ry[EPT], rz[EPT], rsq[EPT], mk[EPT];
    {
        const float* xb = x + (long)bidx * NPTS * 3;
        #pragma unroll
        for (int e = 0; e < EPT; e++) {
            int i = gbase + e;
            float a = xb[3*i + 0];
            float c = xb[3*i + 1];
            float d = xb[3*i + 2];
            rx[e] = a; ry[e] = c; rz[e] = d;
            float s = fmaf(a, a, fmaf(c, c, d * d));
            rsq[e] = s; mk[e] = inf;
            sm->spt[bb][i] = make_float4(-2.0f * a, -2.0f * c, -2.0f * d, s);
        }
    }
    __syncthreads();

    // ---- Prim's MST: two independent chains, one shared barrier per step ----
    // Per-thread body identical to the proven spill-free R2 kernel:
    // scalar sequential argmin, NO u64 register arrays.
    int j = 0;
    int p = 0;

    #pragma unroll 1
    for (int step = 0; step < NPTS - 1; step++) {
        float4 pj = sm->spt[bb][j];          // LDS.128 broadcast within half

        float tm = inf; u32 ti = 0;
        #pragma unroll
        for (int e = 0; e < EPT; e++) {
            int gi = gbase + e;
            bool rem = (gi == j);
            rsq[e] = rem ? inf : rsq[e];     // permanent poison of removed vertex
            float acc = fmaf(pj.x, rx[e], rsq[e] + pj.w);
            acc = fmaf(pj.y, ry[e], acc);
            acc = fmaf(pj.z, rz[e], acc);
            acc = fmaxf(acc, 0.0f);          // >=0 -> u32 bit-order exact
            float m = fminf(mk[e], acc);
            m = rem ? inf : m;
            mk[e] = m;
            if (m < tm) { tm = m; ti = (u32)gi; }
        }

        // warp argmin via two hardware reductions (exact: tm >= 0)
        u32 vb = __float_as_uint(tm);
        u32 r1 = __reduce_min_sync(0xffffffffu, vb);
        u32 ik = (vb == r1) ? ti : 0xffffffffu;
        u32 r2 = __reduce_min_sync(0xffffffffu, ik);
        if (lane == 0) sm->wred[bb][p][lwid] = ((u64)r1 << 32) | (u64)r2;

        __syncthreads();

        // cross-warp final reduce over own half's 8 slots (scalar u64 loads)
        u64 m0 = umin64(sm->wred[bb][p][0], sm->wred[bb][p][1]);
        u64 m1 = umin64(sm->wred[bb][p][2], sm->wred[bb][p][3]);
        u64 m2 = umin64(sm->wred[bb][p][4], sm->wred[bb][p][5]);
        u64 m3 = umin64(sm->wred[bb][p][6], sm->wred[bb][p][7]);
        m0 = umin64(m0, m1); m2 = umin64(m2, m3); m0 = umin64(m0, m2);

        if (ltid == 0) sm->sdeath[bb][step] = __uint_as_float((u32)(m0 >> 32));
        j = (int)(u32)m0;
        p ^= 1;
    }
    __syncthreads();

    // ---- d^2 -> sqrt; pad slot 2047 with +INF ----
    #pragma unroll
    for (int e = 0; e < EPT; e++) {
        int i = gbase + e;
        float d2 = sm->sdeath[bb][i];
        sm->sdeath[bb][i] = (i < NPTS - 1) ? sqrtf(d2) : inf;
    }
    __syncthreads();

    const long bet0     = (long)B * 3 * MAXPTS * 2;
    const long dgm_base = (long)bidx * 3 * MAXPTS * 2;
    const long bet_base = bet0 + (long)bidx * 3 * F;

    // ---- zero-fill H1/H2 + betti rows 1,2; Betti-0 scan (each half its batch) ----
    if (bval) {
        for (int i = ltid; i < 2 * MAXPTS * 2; i += NTH)
            out[dgm_base + MAXPTS * 2 + i] = 0.0f;
        for (int i = ltid; i < 2 * F; i += NTH)
            out[bet_base + F + i] = 0.0f;

        if (ltid < F) {
            float ff = filt[ltid];
            int cnt = 0;
            for (int i = 0; i < NPTS; i += 4) {
                float4 v = *reinterpret_cast<const float4*>(&sm->sdeath[bb][i]);
                cnt += (v.x <= ff) + (v.y <= ff) + (v.z <= ff) + (v.w <= ff);
            }
            out[bet_base + ltid] = (float)(NPTS - cnt);
        }
    }
    __syncthreads();

    // ---- top-100 deaths desc: two independent extractions, shared barrier ----
    int jp = -1;
    p = 0;
    #pragma unroll 1
    for (int k = 0; k < MAXPTS; k++) {
        float tv = 0.0f; u32 ti = 0;
        #pragma unroll
        for (int e = 0; e < EPT; e++) {
            int gi = gbase + e;
            float v = sm->sdeath[bb][gi];
            v = (gi == jp || gi == NPTS - 1) ? 0.0f : v;  // mask pending + INF pad
            if (v > tv) { tv = v; ti = (u32)gi; }
        }
        u32 vb = __float_as_uint(tv);
        u32 r1 = __reduce_max_sync(0xffffffffu, vb);
        u32 ik = (vb == r1) ? ti : 0u;
        u32 r2 = __reduce_max_sync(0xffffffffu, ik);
        if (lane == 0) sm->wred[bb][p][lwid] = ((u64)r1 << 32) | (u64)r2;
        if (ltid == 0 && jp >= 0) sm->sdeath[bb][jp] = 0.0f;   // persist removal

        __syncthreads();

        u64 m0 = umax64(sm->wred[bb][p][0], sm->wred[bb][p][1]);
        u64 m1 = umax64(sm->wred[bb][p][2], sm->wred[bb][p][3]);
        u64 m2 = umax64(sm->wred[bb][p][4], sm->wred[bb][p][5]);
        u64 m3 = umax64(sm->wred[bb][p][6], sm->wred[bb][p][7]);
        m0 = umax64(m0, m1); m2 = umax64(m2, m3); m0 = umax64(m0, m2);

        if (ltid == 0 && bval) {
            out[dgm_base + 2 * k + 0] = 0.0f;                            // birth
            out[dgm_base + 2 * k + 1] = __uint_as_float((u32)(m0 >> 32)); // death
        }
        jp = (int)(u32)m0;
        p ^= 1;
    }
}

extern "C" void kernel_launch(void* const* d_in, const int* in_sizes, int n_in,
                              void* d_out, int out_size)
{
    const float* x    = (const float*)d_in[0];
    const float* filt = (const float*)d_in[1];
    float* out        = (float*)d_out;

    int B = in_sizes[0] / (NPTS * 3);
    int F = in_sizes[1];
    int grid = (B + NBAT - 1) / NBAT;

    cudaFuncSetAttribute(ph_kernel,
                         cudaFuncAttributeMaxDynamicSharedMemorySize,
                         (int)sizeof(Smem));
    ph_kernel<<<grid, NT, sizeof(Smem)>>>(x, filt, out, B, F);
}

// round 7
// speedup vs baseline: 4.4497x; 2.3536x over previous
#include <cuda_runtime.h>
#include <math.h>

#define NPTS   2048
#define NT     128
#define EPT    16
#define NW     (NT/32)      // 4 warps
#define MAXPTS 100
#define F_INF  (__int_as_float(0x7f800000))

typedef unsigned long long u64;
typedef unsigned int       u32;

static __device__ __forceinline__ u64 umin64(u64 a, u64 b) { return a < b ? a : b; }
static __device__ __forceinline__ u64 umax64(u64 a, u64 b) { return a > b ? a : b; }

__global__ __launch_bounds__(NT, 1)
void ph_kernel(const float* __restrict__ x,
               const float* __restrict__ filt,
               float* __restrict__ out,
               int B, int F)
{
    __shared__ float4 spt[NPTS];                 // (-2x,-2y,-2z,|x|^2)
    __shared__ __align__(16) float sdeath[NPTS];
    __shared__ u64 wred[2][NW];

    const int b     = blockIdx.x;
    const int tid   = threadIdx.x;
    const int lane  = tid & 31;
    const int wid   = tid >> 5;
    const int gbase = tid << 4;                  // 16 elements per thread
    const float inf = F_INF;

    const float* xb = x + (long)b * NPTS * 3;

    // ---- load: raw coords in regs, premultiplied float4 in smem ----
    float rx[EPT], ry[EPT], rz[EPT], rsq[EPT], mk[EPT];
    #pragma unroll
    for (int e = 0; e < EPT; e++) {
        int i = gbase + e;
        float a = xb[3*i + 0];
        float c = xb[3*i + 1];
        float d = xb[3*i + 2];
        rx[e] = a; ry[e] = c; rz[e] = d;
        float s = fmaf(a, a, fmaf(c, c, d * d));
        rsq[e] = s; mk[e] = inf;
        spt[i] = make_float4(-2.0f * a, -2.0f * c, -2.0f * d, s);
    }
    __syncthreads();

    // ---- Prim's MST: 2047 steps, one barrier/step ----
    int j = 0;
    int p = 0;

    #pragma unroll 1
    for (int step = 0; step < NPTS - 1; step++) {
        float4 pj = spt[j];                      // LDS.128 broadcast

        #pragma unroll
        for (int e = 0; e < EPT; e++) {
            int gi = gbase + e;
            bool rem = (gi == j);
            float rs = rem ? inf : rsq[e];       // permanent poison of removed vertex
            rsq[e] = rs;
            float acc = fmaf(pj.x, rx[e], rs + pj.w);
            acc = fmaf(pj.y, ry[e], acc);
            acc = fmaf(pj.z, rz[e], acc);
            float m = fminf(mk[e], fabsf(acc));  // |.| keeps >=0 -> u32 bit-order exact
            m = rem ? inf : m;
            mk[e] = m;
        }

        // per-thread argmin over mk[0..15]: pairwise compare-select tree (depth 4)
        float v8[8]; int i8[8];
        #pragma unroll
        for (int e = 0; e < 8; e++) {
            bool c = mk[2*e+1] < mk[2*e];
            v8[e] = c ? mk[2*e+1] : mk[2*e];
            i8[e] = c ? 2*e+1 : 2*e;
        }
        float v4[4]; int i4[4];
        #pragma unroll
        for (int e = 0; e < 4; e++) {
            bool c = v8[2*e+1] < v8[2*e];
            v4[e] = c ? v8[2*e+1] : v8[2*e];
            i4[e] = c ? i8[2*e+1] : i8[2*e];
        }
        bool c0 = v4[1] < v4[0];
        float va = c0 ? v4[1] : v4[0];  int ia = c0 ? i4[1] : i4[0];
        bool c1 = v4[3] < v4[2];
        float vc = c1 ? v4[3] : v4[2];  int ic = c1 ? i4[3] : i4[2];
        bool c2 = vc < va;
        float tm = c2 ? vc : va;        int te = c2 ? ic : ia;
        u32 ti = (u32)(gbase + te);

        // warp argmin via two hardware reductions (exact: tm >= 0)
        u32 vb = __float_as_uint(tm);
        u32 r1 = __reduce_min_sync(0xffffffffu, vb);
        u32 ik = (vb == r1) ? ti : 0xffffffffu;
        u32 r2 = __reduce_min_sync(0xffffffffu, ik);
        if (lane == 0) wred[p][wid] = ((u64)r1 << 32) | (u64)r2;

        __syncthreads();

        // cross-warp final: 2-level u64 min tree over 4 slots (redundant/thread)
        u64 m0 = umin64(wred[p][0], wred[p][1]);
        u64 m1 = umin64(wred[p][2], wred[p][3]);
        m0 = umin64(m0, m1);

        if (tid == 0) sdeath[step] = __uint_as_float((u32)(m0 >> 32));  // d^2 death
        j = (int)(u32)m0;
        p ^= 1;
    }
    __syncthreads();

    // ---- d^2 -> death = sqrt(d2); pad slot 2047 with +INF ----
    #pragma unroll
    for (int e = 0; e < EPT; e++) {
        int i = gbase + e;
        float d2 = sdeath[i];
        sdeath[i] = (i < NPTS - 1) ? sqrtf(d2) : inf;
    }
    __syncthreads();

    const long dgm_base = (long)b * 3 * MAXPTS * 2;                     // diagrams [B,3,100,2]
    const long bet_base = (long)B * 3 * MAXPTS * 2 + (long)b * 3 * F;   // betti    [B,3,F]

    // ---- zero-fill H1/H2 diagram slices and betti rows 1,2 ----
    for (int i = tid; i < 2 * MAXPTS * 2; i += NT)
        out[dgm_base + MAXPTS * 2 + i] = 0.0f;
    for (int i = tid; i < 2 * F; i += NT)
        out[bet_base + F + i] = 0.0f;

    // ---- Betti-0: one threshold per thread, float4 smem scan (pad=INF never counts) ----
    if (tid < F) {
        float ff = filt[tid];
        int cnt = 0;
        for (int i = 0; i < NPTS; i += 4) {
            float4 v = *reinterpret_cast<const float4*>(&sdeath[i]);
            cnt += (v.x <= ff) + (v.y <= ff) + (v.z <= ff) + (v.w <= ff);
        }
        out[bet_base + tid] = (float)(NPTS - cnt);
    }
    __syncthreads();

    // ---- top-100 deaths desc: iterative max extraction ----
    int jp = -1;
    p = 0;
    #pragma unroll 1
    for (int k = 0; k < MAXPTS; k++) {
        float mv[EPT];
        #pragma unroll
        for (int e = 0; e < EPT; e++) {
            int gi = gbase + e;
            float v = sdeath[gi];
            mv[e] = (gi == jp || gi == NPTS - 1) ? 0.0f : v;  // mask pending + INF pad
        }
        // pairwise compare-select max tree
        float v8[8]; int i8[8];
        #pragma unroll
        for (int e = 0; e < 8; e++) {
            bool c = mv[2*e+1] > mv[2*e];
            v8[e] = c ? mv[2*e+1] : mv[2*e];
            i8[e] = c ? 2*e+1 : 2*e;
        }
        float v4[4]; int i4[4];
        #pragma unroll
        for (int e = 0; e < 4; e++) {
            bool c = v8[2*e+1] > v8[2*e];
            v4[e] = c ? v8[2*e+1] : v8[2*e];
            i4[e] = c ? i8[2*e+1] : i8[2*e];
        }
        bool c0 = v4[1] > v4[0];
        float va = c0 ? v4[1] : v4[0];  int ia = c0 ? i4[1] : i4[0];
        bool c1 = v4[3] > v4[2];
        float vc = c1 ? v4[3] : v4[2];  int ic = c1 ? i4[3] : i4[2];
        bool c2 = vc > va;
        float tv = c2 ? vc : va;        int te = c2 ? ic : ia;
        u32 ti = (u32)(gbase + te);

        u32 vb = __float_as_uint(tv);
        u32 r1 = __reduce_max_sync(0xffffffffu, vb);
        u32 ik = (vb == r1) ? ti : 0u;
        u32 r2 = __reduce_max_sync(0xffffffffu, ik);
        if (lane == 0) wred[p][wid] = ((u64)r1 << 32) | (u64)r2;
        if (tid == 0 && jp >= 0) sdeath[jp] = 0.0f;   // persist removal

        __syncthreads();

        u64 m0 = umax64(wred[p][0], wred[p][1]);
        u64 m1 = umax64(wred[p][2], wred[p][3]);
        m0 = umax64(m0, m1);

        if (tid == 0) {
            out[dgm_base + 2 * k + 0] = 0.0f;                            // birth
            out[dgm_base + 2 * k + 1] = __uint_as_float((u32)(m0 >> 32)); // death
        }
        jp = (int)(u32)m0;
        p ^= 1;
    }
}

extern "C" void kernel_launch(void* const* d_in, const int* in_sizes, int n_in,
                              void* d_out, int out_size)
{
    const float* x    = (const float*)d_in[0];
    const float* filt = (const float*)d_in[1];
    float* out        = (float*)d_out;

    int B = in_sizes[0] / (NPTS * 3);
    int F = in_sizes[1];

    ph_kernel<<<B, NT>>>(x, filt, out, B, F);
}

// round 8
// speedup vs baseline: 5.0434x; 1.1334x over previous
#include <cuda_runtime.h>
#include <math.h>

#define NPTS   2048
#define NT     128
#define EPT    16
#define EPT2   8
#define NW     (NT/32)      // 4 warps
#define MAXPTS 100
#define PH1    1024         // phase-1 steps
#define F_INF  (__int_as_float(0x7f800000))

typedef unsigned long long u64;
typedef unsigned int       u32;

static __device__ __forceinline__ u64 umin64(u64 a, u64 b) { return a < b ? a : b; }
static __device__ __forceinline__ u64 umax64(u64 a, u64 b) { return a > b ? a : b; }

struct Smem {
    float4 spt [NPTS];        // phase1 broadcast table: (-2x,-2y,-2z,|x|^2)
    float4 spt2[PH1];         // phase2 broadcast table: raw (x,y,z,|x|^2)
    float  smk2[PH1];         // staged mk for phase2
    float  sdeath[NPTS];
    u64    wred[2][NW];
    int    scnt;
};

__global__ __launch_bounds__(NT, 1)
void ph_kernel(const float* __restrict__ x,
               const float* __restrict__ filt,
               float* __restrict__ out,
               int B, int F)
{
    extern __shared__ char smraw[];
    Smem* sm = reinterpret_cast<Smem*>(smraw);

    const int b     = blockIdx.x;
    const int tid   = threadIdx.x;
    const int lane  = tid & 31;
    const int wid   = tid >> 5;
    const int gbase = tid << 4;
    const float inf = F_INF;

    const float* xb = x + (long)b * NPTS * 3;

    // ---- load: raw coords in regs, premultiplied float4 in smem ----
    float rx[EPT], ry[EPT], rz[EPT], rsq[EPT], mk[EPT];
    #pragma unroll
    for (int e = 0; e < EPT; e++) {
        int i = gbase + e;
        float a = xb[3*i + 0];
        float c = xb[3*i + 1];
        float d = xb[3*i + 2];
        rx[e] = a; ry[e] = c; rz[e] = d;
        float s = fmaf(a, a, fmaf(c, c, d * d));
        rsq[e] = s; mk[e] = inf;
        sm->spt[i] = make_float4(-2.0f * a, -2.0f * c, -2.0f * d, s);
    }
    if (tid == 0) sm->scnt = 0;
    __syncthreads();

    int j = 0;
    int p = 0;

    // =================== PHASE 1: steps 0..1023, EPT=16 ===================
    #pragma unroll 1
    for (int step = 0; step < PH1; step++) {
        float4 pj = sm->spt[j];

        #pragma unroll
        for (int e = 0; e < EPT; e++) {
            int gi = gbase + e;
            bool rem = (gi == j);
            float rs = rem ? inf : rsq[e];
            rsq[e] = rs;
            float acc = fmaf(pj.x, rx[e], rs + pj.w);
            acc = fmaf(pj.y, ry[e], acc);
            acc = fmaf(pj.z, rz[e], acc);
            float mi = rem ? inf : mk[e];
            mk[e] = fminf(mi, fabsf(acc));   // >=0 -> u32 bit-order exact
        }

        // per-thread argmin: pairwise compare-select tree
        float v8[8]; int i8[8];
        #pragma unroll
        for (int e = 0; e < 8; e++) {
            bool c = mk[2*e+1] < mk[2*e];
            v8[e] = c ? mk[2*e+1] : mk[2*e];
            i8[e] = c ? 2*e+1 : 2*e;
        }
        float v4[4]; int i4[4];
        #pragma unroll
        for (int e = 0; e < 4; e++) {
            bool c = v8[2*e+1] < v8[2*e];
            v4[e] = c ? v8[2*e+1] : v8[2*e];
            i4[e] = c ? i8[2*e+1] : i8[2*e];
        }
        bool c0 = v4[1] < v4[0];
        float va = c0 ? v4[1] : v4[0];  int ia = c0 ? i4[1] : i4[0];
        bool c1 = v4[3] < v4[2];
        float vc = c1 ? v4[3] : v4[2];  int ic = c1 ? i4[3] : i4[2];
        bool c2 = vc < va;
        float tm = c2 ? vc : va;
        u32 ti = (u32)(gbase + (c2 ? ic : ia));

        // single REDUX; matching lanes STS.64 (same value, any index valid)
        u32 vb = __float_as_uint(tm);
        u32 r1 = __reduce_min_sync(0xffffffffu, vb);
        if (vb == r1) sm->wred[p][wid] = ((u64)r1 << 32) | (u64)ti;

        __syncthreads();

        u64 m0 = umin64(sm->wred[p][0], sm->wred[p][1]);
        u64 m1 = umin64(sm->wred[p][2], sm->wred[p][3]);
        m0 = umin64(m0, m1);
        if (tid == 0) sm->sdeath[step] = __uint_as_float((u32)(m0 >> 32));
        j = (int)(u32)m0;
        p ^= 1;
    }

    // =================== COMPACTION at step 1024 ===================
    // Apply pending poison for last winner j; stash its coords at pad slot 1023.
    #pragma unroll
    for (int e = 0; e < EPT; e++) {
        if (gbase + e == j) { rsq[e] = inf; mk[e] = inf; }
    }
    if (tid == 0) {
        float4 pjp = sm->spt[j];   // premultiplied; recover raw
        sm->spt2[PH1 - 1] = make_float4(-0.5f * pjp.x, -0.5f * pjp.y,
                                        -0.5f * pjp.z, pjp.w);
        sm->smk2[PH1 - 1] = inf;
    }
    // Stage alive vertices (mk < inf) into spt2/smk2; order irrelevant.
    {
        int na = 0;
        #pragma unroll
        for (int e = 0; e < EPT; e++) na += (mk[e] != inf);
        int base = atomicAdd(&sm->scnt, na);
        #pragma unroll
        for (int e = 0; e < EPT; e++) {
            if (mk[e] != inf) {
                sm->spt2[base] = make_float4(rx[e], ry[e], rz[e], rsq[e]);
                sm->smk2[base] = mk[e];
                base++;
            }
        }
    }
    __syncthreads();

    // Reload registers for phase 2 (EPT2=8)
    const int gbase2 = tid << 3;
    float qx[EPT2], qy[EPT2], qz[EPT2], qs[EPT2], qm[EPT2];
    #pragma unroll
    for (int e = 0; e < EPT2; e++) {
        int i = gbase2 + e;
        float4 q = sm->spt2[i];
        qx[e] = q.x; qy[e] = q.y; qz[e] = q.z;
        bool pad = (i == PH1 - 1);              // pad slot holds last winner's coords
        qs[e] = pad ? inf : q.w;
        qm[e] = pad ? inf : sm->smk2[i];
    }
    j = PH1 - 1;                                 // broadcast last winner first

    // =================== PHASE 2: steps 1024..2046, EPT=8 ===================
    #pragma unroll 1
    for (int s = 0; s < NPTS - 1 - PH1; s++) {
        float4 q = sm->spt2[j];
        float m2x = -2.0f * q.x;
        float m2y = -2.0f * q.y;
        float m2z = -2.0f * q.z;
        float bse = q.w;

        #pragma unroll
        for (int e = 0; e < EPT2; e++) {
            int gi = gbase2 + e;
            bool rem = (gi == j);
            float rs = rem ? inf : qs[e];
            qs[e] = rs;
            float acc = fmaf(m2x, qx[e], rs + bse);
            acc = fmaf(m2y, qy[e], acc);
            acc = fmaf(m2z, qz[e], acc);
            float mi = rem ? inf : qm[e];
            qm[e] = fminf(mi, fabsf(acc));
        }

        float v4[4]; int i4[4];
        #pragma unroll
        for (int e = 0; e < 4; e++) {
            bool c = qm[2*e+1] < qm[2*e];
            v4[e] = c ? qm[2*e+1] : qm[2*e];
            i4[e] = c ? 2*e+1 : 2*e;
        }
        bool c0 = v4[1] < v4[0];
        float va = c0 ? v4[1] : v4[0];  int ia = c0 ? i4[1] : i4[0];
        bool c1 = v4[3] < v4[2];
        float vc = c1 ? v4[3] : v4[2];  int ic = c1 ? i4[3] : i4[2];
        bool c2 = vc < va;
        float tm = c2 ? vc : va;
        u32 ti = (u32)(gbase2 + (c2 ? ic : ia));

        u32 vb = __float_as_uint(tm);
        u32 r1 = __reduce_min_sync(0xffffffffu, vb);
        if (vb == r1) sm->wred[p][wid] = ((u64)r1 << 32) | (u64)ti;

        __syncthreads();

        u64 m0 = umin64(sm->wred[p][0], sm->wred[p][1]);
        u64 m1 = umin64(sm->wred[p][2], sm->wred[p][3]);
        m0 = umin64(m0, m1);
        if (tid == 0) sm->sdeath[PH1 + s] = __uint_as_float((u32)(m0 >> 32));
        j = (int)(u32)m0;
        p ^= 1;
    }
    __syncthreads();

    // ---- d^2 -> death = sqrt(d2); pad slot 2047 with +INF ----
    #pragma unroll
    for (int e = 0; e < EPT; e++) {
        int i = gbase + e;
        float d2 = sm->sdeath[i];
        sm->sdeath[i] = (i < NPTS - 1) ? sqrtf(d2) : inf;
    }
    __syncthreads();

    const long dgm_base = (long)b * 3 * MAXPTS * 2;                     // diagrams [B,3,100,2]
    const long bet_base = (long)B * 3 * MAXPTS * 2 + (long)b * 3 * F;   // betti    [B,3,F]

    // ---- zero-fill H1/H2 diagram slices and betti rows 1,2 ----
    for (int i = tid; i < 2 * MAXPTS * 2; i += NT)
        out[dgm_base + MAXPTS * 2 + i] = 0.0f;
    for (int i = tid; i < 2 * F; i += NT)
        out[bet_base + F + i] = 0.0f;

    // ---- Betti-0: one threshold per thread, float4 smem scan ----
    if (tid < F) {
        float ff = filt[tid];
        int cnt = 0;
        for (int i = 0; i < NPTS; i += 4) {
            float4 v = *reinterpret_cast<const float4*>(&sm->sdeath[i]);
            cnt += (v.x <= ff) + (v.y <= ff) + (v.z <= ff) + (v.w <= ff);
        }
        out[bet_base + tid] = (float)(NPTS - cnt);
    }
    __syncthreads();

    // ---- top-100 deaths desc: iterative max extraction (single REDUX) ----
    int jp = -1;
    p = 0;
    #pragma unroll 1
    for (int k = 0; k < MAXPTS; k++) {
        float mv[EPT];
        #pragma unroll
        for (int e = 0; e < EPT; e++) {
            int gi = gbase + e;
            float v = sm->sdeath[gi];
            mv[e] = (gi == jp || gi == NPTS - 1) ? 0.0f : v;
        }
        float v8[8]; int i8[8];
        #pragma unroll
        for (int e = 0; e < 8; e++) {
            bool c = mv[2*e+1] > mv[2*e];
            v8[e] = c ? mv[2*e+1] : mv[2*e];
            i8[e] = c ? 2*e+1 : 2*e;
        }
        float v4[4]; int i4[4];
        #pragma unroll
        for (int e = 0; e < 4; e++) {
            bool c = v8[2*e+1] > v8[2*e];
            v4[e] = c ? v8[2*e+1] : v8[2*e];
            i4[e] = c ? i8[2*e+1] : i8[2*e];
        }
        bool c0 = v4[1] > v4[0];
        float va = c0 ? v4[1] : v4[0];  int ia = c0 ? i4[1] : i4[0];
        bool c1 = v4[3] > v4[2];
        float vc = c1 ? v4[3] : v4[2];  int ic = c1 ? i4[3] : i4[2];
        bool c2 = vc > va;
        float tv = c2 ? vc : va;
        u32 ti = (u32)(gbase + (c2 ? ic : ia));

        u32 vb = __float_as_uint(tv);
        u32 r1 = __reduce_max_sync(0xffffffffu, vb);
        if (vb == r1) sm->wred[p][wid] = ((u64)r1 << 32) | (u64)ti;
        if (tid == 0 && jp >= 0) sm->sdeath[jp] = 0.0f;

        __syncthreads();

        u64 m0 = umax64(sm->wred[p][0], sm->wred[p][1]);
        u64 m1 = umax64(sm->wred[p][2], sm->wred[p][3]);
        m0 = umax64(m0, m1);

        if (tid == 0) {
            out[dgm_base + 2 * k + 0] = 0.0f;
            out[dgm_base + 2 * k + 1] = __uint_as_float((u32)(m0 >> 32));
        }
        jp = (int)(u32)m0;
        p ^= 1;
    }
}

extern "C" void kernel_launch(void* const* d_in, const int* in_sizes, int n_in,
                              void* d_out, int out_size)
{
    const float* x    = (const float*)d_in[0];
    const float* filt = (const float*)d_in[1];
    float* out        = (float*)d_out;

    int B = in_sizes[0] / (NPTS * 3);
    int F = in_sizes[1];

    cudaFuncSetAttribute(ph_kernel,
                         cudaFuncAttributeMaxDynamicSharedMemorySize,
                         (int)sizeof(Smem));
    ph_kernel<<<B, NT, sizeof(Smem)>>>(x, filt, out, B, F);
}